// round 4
// baseline (speedup 1.0000x reference)
#include <cuda_runtime.h>
#include <cstdint>
#include <math.h>

// ---------------------------------------------------------------------------
// PerturbedSelect (verified R2/R3, rel_err 5.6e-7):
//   bits[i] = o0^o1 of threefry2x32((0,42),(0,i))   [jax partitionable PRNG]
//   g = -log(-log(u(bits))) ; idx = argmax_d logits[k,d] + sigma*g
//   S[k,d] = count/1000 ; Y = X @ S^T
// R4: pipe rebalance — all cipher adds forced to the fma pipe (IMAD via
//     mad.lo with runtime multiplier), cipher specialized for x0=0 / k0=0.
//     alu pipe now carries only SHF/LOP3 (~43/elem vs ~56/elem).
// ---------------------------------------------------------------------------

#define NSAMP 1000
#define KOUT  64
#define DDIM  4096
#define BATCH 2048
#define NROWS (NSAMP * KOUT)          /* 64000 */

#define K1C 42u
#define K2C (42u ^ 0x1BD11BDAu)

__device__ int      g_counts[KOUT * DDIM];
__device__ float    g_St[DDIM * KOUT];
__device__ uint32_t g_mn_u, g_mx_u;   // order-preserving encoded float min/max

static __device__ __forceinline__ uint32_t enc_f(float x) {
    uint32_t u = __float_as_uint(x);
    return (u & 0x80000000u) ? ~u : (u | 0x80000000u);
}
static __device__ __forceinline__ float dec_f(uint32_t e) {
    uint32_t u = (e & 0x80000000u) ? (e ^ 0x80000000u) : ~e;
    return __uint_as_float(u);
}

static __device__ __forceinline__ uint32_t rotl32(uint32_t x, int d) {
    return __funnelshift_l(x, x, d);
}

// add forced onto the fma pipe: IMAD r = a*one + b, `one` is a kernel param
// (runtime value, not foldable by ptxas).
static __device__ __forceinline__ uint32_t addp(uint32_t a, uint32_t b, uint32_t one) {
    uint32_t r;
    asm("mad.lo.u32 %0, %1, %2, %3;" : "=r"(r) : "r"(a), "r"(one), "r"(b));
    return r;
}

// Exact jax gumbel from raw bits; double logs are correctly rounded and
// immune to --use_fast_math. Used ONLY for the rare candidates (~1-2/row).
static __device__ __forceinline__ float gumbel_f32(uint32_t bits) {
    const float tiny = 1.17549435082228751e-38f;
    float f = __uint_as_float((bits >> 9) | 0x3f800000u) - 1.0f;  // exact
    float u = fmaxf(tiny, __fadd_rn(f, tiny));
    float L1 = (float)log((double)u);
    float L2 = (float)log((double)(-L1));
    return -L2;
}

#define SIGMA_F ((float)(10.0 * 0.99998))

// ---------------------------------------------------------------- kernel 1
__global__ void zero_init_kernel() {
    int i = blockIdx.x * blockDim.x + threadIdx.x;
    if (i < KOUT * DDIM) g_counts[i] = 0;
    if (i == 0) { g_mx_u = 0u; g_mn_u = 0xFFFFFFFFu; }
}

// ---------------------------------------------------------------- kernel 2
__global__ void range_kernel(const float* __restrict__ logits) {
    float mn = 3.4e38f, mx = -3.4e38f;
    for (int i = blockIdx.x * blockDim.x + threadIdx.x; i < KOUT * DDIM;
         i += gridDim.x * blockDim.x) {
        float v = logits[i];
        mn = fminf(mn, v); mx = fmaxf(mx, v);
    }
    for (int o = 16; o; o >>= 1) {
        mn = fminf(mn, __shfl_xor_sync(~0u, mn, o));
        mx = fmaxf(mx, __shfl_xor_sync(~0u, mx, o));
    }
    if ((threadIdx.x & 31) == 0) {
        atomicMin(&g_mn_u, enc_f(mn));
        atomicMax(&g_mx_u, enc_f(mx));
    }
}

// ---------------------------------------------------------------- kernel 3
// One CTA per (sample,k) row. Pass 1: threefry all 4096 bits into registers
// (adds on fma pipe, shifts/xors on alu pipe), integer max over raw bits.
// Threshold (float MUFU, conservative) selects ~1-2 candidates/row for exact
// evaluation; winner counted via atomicAdd.
#define TPB 256
#define DPT (DDIM / TPB)   /* 16 */

__global__ __launch_bounds__(TPB) void argmax_kernel(const float* __restrict__ logits,
                                                     uint32_t one) {
    const int row = blockIdx.x;
    const int k = row & (KOUT - 1);
    const uint32_t base = (uint32_t)row * (uint32_t)DDIM;   // < 2^32
    const int t = threadIdx.x;
    // x1_init = counter + k1 = (base + t*DPT + j) + 42, folded into one const
    const uint32_t Cbase = base + (uint32_t)t * DPT + K1C;

    uint32_t m[DPT];
#pragma unroll
    for (int j = 0; j < DPT; j++) {
        uint32_t x1v = addp(Cbase, (uint32_t)j, one);
        // round 1 specialized: x0_init = 0  ->  x0 = x1v
        uint32_t x0 = x1v;
        uint32_t x1 = rotl32(x1v, 13) ^ x0;
#define RNDP(r) { x0 = addp(x0, x1, one); x1 = rotl32(x1, r) ^ x0; }
        RNDP(15) RNDP(26) RNDP(6)
        x0 = addp(x0, K1C, one);      x1 = addp(x1, K2C + 1u, one);
        RNDP(17) RNDP(29) RNDP(16) RNDP(24)
        x0 = addp(x0, K2C, one);      x1 = addp(x1, 2u, one);
        RNDP(13) RNDP(15) RNDP(26) RNDP(6)
        /* x0 += k0 (0): skipped */   x1 = addp(x1, K1C + 3u, one);
        RNDP(17) RNDP(29) RNDP(16) RNDP(24)
        x0 = addp(x0, K1C, one);      x1 = addp(x1, K2C + 4u, one);
        RNDP(13) RNDP(15) RNDP(26) RNDP(6)
        x0 = addp(x0, K2C, one);      x1 = addp(x1, 5u, one);
#undef RNDP
        m[j] = x0 ^ x1;               // raw 32-bit; order == (m>>9) order
    }

    // tree max for ILP
    uint32_t r8[8];
#pragma unroll
    for (int j = 0; j < 8; j++) r8[j] = max(m[j], m[j + 8]);
#pragma unroll
    for (int j = 0; j < 4; j++) r8[j] = max(r8[j], r8[j + 4]);
    uint32_t mymax = max(max(r8[0], r8[1]), max(r8[2], r8[3]));

    for (int o = 16; o; o >>= 1) mymax = max(mymax, __shfl_xor_sync(~0u, mymax, o));

    __shared__ uint32_t swm[TPB / 32];
    __shared__ uint32_t s_mt9;
    __shared__ unsigned long long s_best;
    if ((t & 31) == 0) swm[t >> 5] = mymax;
    if (t == 0) s_best = 0ull;
    __syncthreads();

    if (t == 0) {
        uint32_t mmax = swm[0];
#pragma unroll
        for (int w = 1; w < TPB / 32; w++) mmax = max(mmax, swm[w]);
        uint32_t mm9 = mmax >> 9;
        // Candidate window in u-space: u_t = u_max^{exp(W)}, W = range/sigma + slack.
        // MUFU-fast with 64-tick downward slack: threshold is only a pruning
        // bound — pass-2 exact eval decides the argmax.
        float W  = (dec_f(g_mx_u) - dec_f(g_mn_u)) * (1.0f / SIGMA_F) + 2e-3f;
        float um = fmaxf(__uint_as_float(mm9 | 0x3f800000u) - 1.0f, 1e-30f);
        float ut = __expf(__expf(W) * __logf(um));
        long long mt = (long long)floorf(ut * 8388608.0f) - 64;
        if (mt < 0) mt = 0;
        if ((unsigned long long)mt > mm9) mt = mm9;
        s_mt9 = (uint32_t)mt << 9;
    }
    __syncthreads();

    const uint32_t mt9 = s_mt9;
    unsigned long long best = 0ull;
#pragma unroll
    for (int j = 0; j < DPT; j++) {
        if (m[j] >= mt9) {
            uint32_t d = (uint32_t)t * DPT + j;
            float g = gumbel_f32(m[j]);
            // z exactly as XLA: separate f32 mul + add (no FMA contraction)
            float z = __fadd_rn(logits[k * DDIM + (int)d], __fmul_rn(SIGMA_F, g));
            uint32_t oz = __float_as_uint(z);
            oz = (oz & 0x80000000u) ? ~oz : (oz | 0x80000000u);  // order-preserving
            unsigned long long key =
                ((unsigned long long)oz << 32) | (uint32_t)(0xFFFFFFFFu - d);
            best = max(best, key);   // tie -> lowest index wins
        }
    }
    for (int o = 16; o; o >>= 1) best = max(best, __shfl_xor_sync(~0u, best, o));
    if ((t & 31) == 0) atomicMax(&s_best, best);
    __syncthreads();
    if (t == 0) {
        int d = (int)(0xFFFFFFFFu - (uint32_t)(s_best & 0xFFFFFFFFu));
        atomicAdd(&g_counts[(k << 12) + d], 1);
    }
}

// ---------------------------------------------------------------- kernel 4
__global__ void build_st_kernel() {
    int i = blockIdx.x * blockDim.x + threadIdx.x;   // i = k*4096 + d
    if (i < KOUT * DDIM) {
        int k = i >> 12, d = i & (DDIM - 1);
        g_St[d * KOUT + k] = (float)g_counts[i] * 0.001f;
    }
}

// ---------------------------------------------------------------- kernel 5
// Y[2048,64] = X[2048,4096] @ St[4096,64]
#define TB_M 16
#define DC   64

__global__ __launch_bounds__(128) void gemm_kernel(const float* __restrict__ X,
                                                   float* __restrict__ Y) {
    __shared__ float Xs[TB_M][DC + 4];
    __shared__ float Ss[DC][KOUT + 4];
    const int t = threadIdx.x;
    const int brow0 = blockIdx.x * TB_M;
    const int tr = t >> 4;          // 0..7  -> rows tr*2, tr*2+1
    const int tk = t & 15;          // 0..15 -> cols tk*4 .. tk*4+3
    float acc[2][4] = {};

    for (int d0 = 0; d0 < DDIM; d0 += DC) {
#pragma unroll
        for (int l = 0; l < 8; l++) {
            int idx = t + l * 128;
            Xs[idx >> 6][idx & 63] = X[(brow0 + (idx >> 6)) * DDIM + d0 + (idx & 63)];
        }
#pragma unroll
        for (int l = 0; l < 32; l++) {
            int idx = t + l * 128;
            Ss[idx >> 6][idx & 63] = g_St[(d0 + (idx >> 6)) * KOUT + (idx & 63)];
        }
        __syncthreads();
#pragma unroll
        for (int dd = 0; dd < DC; dd++) {
            float x0 = Xs[tr * 2 + 0][dd];
            float x1 = Xs[tr * 2 + 1][dd];
            float4 s = *(const float4*)&Ss[dd][tk * 4];
            acc[0][0] += x0 * s.x; acc[0][1] += x0 * s.y;
            acc[0][2] += x0 * s.z; acc[0][3] += x0 * s.w;
            acc[1][0] += x1 * s.x; acc[1][1] += x1 * s.y;
            acc[1][2] += x1 * s.z; acc[1][3] += x1 * s.w;
        }
        __syncthreads();
    }
#pragma unroll
    for (int r = 0; r < 2; r++)
#pragma unroll
        for (int c = 0; c < 4; c++)
            Y[(brow0 + tr * 2 + r) * KOUT + tk * 4 + c] = acc[r][c];
}

// ---------------------------------------------------------------------------
extern "C" void kernel_launch(void* const* d_in, const int* in_sizes, int n_in,
                              void* d_out, int out_size) {
    const float* X = (const float*)d_in[0];
    const float* logits = (const float*)d_in[1];
    if (n_in >= 2 && in_sizes[0] == KOUT * DDIM) {   // defensive: swapped order
        X = (const float*)d_in[1];
        logits = (const float*)d_in[0];
    }
    float* Y = (float*)d_out;

    zero_init_kernel<<<(KOUT * DDIM + 255) / 256, 256>>>();
    range_kernel<<<64, 256>>>(logits);
    argmax_kernel<<<NROWS, TPB>>>(logits, 1u);
    build_st_kernel<<<(KOUT * DDIM + 255) / 256, 256>>>();
    gemm_kernel<<<BATCH / TB_M, 128>>>(X, Y);
}

// round 8
// speedup vs baseline: 1.0148x; 1.0148x over previous
#include <cuda_runtime.h>
#include <cstdint>
#include <math.h>

// ---------------------------------------------------------------------------
// PerturbedSelect (verified R2-R4, rel_err 5.6e-7):
//   bits[i] = o0^o1 of threefry2x32((0,42),(0,i))   [jax partitionable PRNG]
//   g = -log(-log(u(bits))) ; idx = argmax_d logits[k,d] + sigma*g
//   S[k,d] = count/1000 ; Y = X @ S^T
// R5: revert cipher to R3 plain-C++ (R4 IMAD-forcing regressed 9%); reorder
//     launches so argmax lands in ncu's sampled slot (#4); bigger GEMM tile.
// ---------------------------------------------------------------------------

#define NSAMP 1000
#define KOUT  64
#define DDIM  4096
#define BATCH 2048
#define NROWS (NSAMP * KOUT)          /* 64000 */

__device__ int      g_counts[KOUT * DDIM];
__device__ float    g_St[DDIM * KOUT];
// Range atomics are idempotent across graph replays (same data -> same
// min/max), so static init is sufficient; no per-run reset.
__device__ uint32_t g_mn_u = 0xFFFFFFFFu;
__device__ uint32_t g_mx_u = 0u;

static __device__ __forceinline__ uint32_t enc_f(float x) {
    uint32_t u = __float_as_uint(x);
    return (u & 0x80000000u) ? ~u : (u | 0x80000000u);
}
static __device__ __forceinline__ float dec_f(uint32_t e) {
    uint32_t u = (e & 0x80000000u) ? (e ^ 0x80000000u) : ~e;
    return __uint_as_float(u);
}

static __device__ __forceinline__ uint32_t rotl32(uint32_t x, int d) {
    return __funnelshift_l(x, x, d);
}

// Threefry-2x32, 20 rounds, key (0, 42) — matches jax threefry2x32 lowering.
// Plain C++: let ptxas pick the IMAD/IADD3 mix (proven fastest, R3).
static __device__ __forceinline__ void threefry(uint32_t x0, uint32_t x1,
                                                uint32_t& o0, uint32_t& o1) {
    const uint32_t k0 = 0u, k1 = 42u, k2 = 0u ^ 42u ^ 0x1BD11BDAu;
    x0 += k0; x1 += k1;
#define RND(r) { x0 += x1; x1 = rotl32(x1, r); x1 ^= x0; }
    RND(13) RND(15) RND(26) RND(6)
    x0 += k1; x1 += k2 + 1u;
    RND(17) RND(29) RND(16) RND(24)
    x0 += k2; x1 += k0 + 2u;
    RND(13) RND(15) RND(26) RND(6)
    x0 += k0; x1 += k1 + 3u;
    RND(17) RND(29) RND(16) RND(24)
    x0 += k1; x1 += k2 + 4u;
    RND(13) RND(15) RND(26) RND(6)
    x0 += k2; x1 += k0 + 5u;
#undef RND
    o0 = x0; o1 = x1;
}

// Exact jax gumbel from raw bits; double logs are correctly rounded and
// immune to --use_fast_math. Used ONLY for the rare candidates (~1-2/row).
static __device__ __forceinline__ float gumbel_f32(uint32_t bits) {
    const float tiny = 1.17549435082228751e-38f;
    float f = __uint_as_float((bits >> 9) | 0x3f800000u) - 1.0f;  // exact
    float u = fmaxf(tiny, __fadd_rn(f, tiny));
    float L1 = (float)log((double)u);
    float L2 = (float)log((double)(-L1));
    return -L2;
}

#define SIGMA_F ((float)(10.0 * 0.99998))

// ---------------------------------------------------------------- launch 1
__global__ void range_kernel(const float* __restrict__ logits) {
    float mn = 3.4e38f, mx = -3.4e38f;
    for (int i = blockIdx.x * blockDim.x + threadIdx.x; i < KOUT * DDIM;
         i += gridDim.x * blockDim.x) {
        float v = logits[i];
        mn = fminf(mn, v); mx = fmaxf(mx, v);
    }
    for (int o = 16; o; o >>= 1) {
        mn = fminf(mn, __shfl_xor_sync(~0u, mn, o));
        mx = fmaxf(mx, __shfl_xor_sync(~0u, mx, o));
    }
    if ((threadIdx.x & 31) == 0) {
        atomicMin(&g_mn_u, enc_f(mn));
        atomicMax(&g_mx_u, enc_f(mx));
    }
}

// ------------------------------------------------------------ launches 2+3
// Split in two halves so argmax_kernel sits at launch slot #4 (the one the
// fixed ncu -s/-c window samples).
__global__ void zero_half_kernel(int off) {
    int i = off + blockIdx.x * blockDim.x + threadIdx.x;
    g_counts[i] = 0;
}

// ---------------------------------------------------------------- launch 4
// One CTA per (sample,k) row. Pass 1: threefry all 4096 bits into registers,
// integer max over raw bits. Threshold (float MUFU, conservative) selects
// ~1-2 candidates/row for exact evaluation; winner counted via atomicAdd.
#define TPB 256
#define DPT (DDIM / TPB)   /* 16 */

__global__ __launch_bounds__(TPB) void argmax_kernel(const float* __restrict__ logits) {
    const int row = blockIdx.x;
    const int k = row & (KOUT - 1);
    const uint32_t base = (uint32_t)row * (uint32_t)DDIM;   // < 2^32
    const int t = threadIdx.x;

    uint32_t m[DPT];
#pragma unroll
    for (int j = 0; j < DPT; j++) {
        uint32_t i = base + (uint32_t)t * DPT + j;
        uint32_t o0, o1;
        threefry(0u, i, o0, o1);
        m[j] = o0 ^ o1;                 // raw 32-bit; order == (m>>9) order
    }

    // tree max for ILP
    uint32_t r8[8];
#pragma unroll
    for (int j = 0; j < 8; j++) r8[j] = max(m[j], m[j + 8]);
#pragma unroll
    for (int j = 0; j < 4; j++) r8[j] = max(r8[j], r8[j + 4]);
    uint32_t mymax = max(max(r8[0], r8[1]), max(r8[2], r8[3]));

    for (int o = 16; o; o >>= 1) mymax = max(mymax, __shfl_xor_sync(~0u, mymax, o));

    __shared__ uint32_t swm[TPB / 32];
    __shared__ uint32_t s_mt9;
    __shared__ unsigned long long s_best;
    if ((t & 31) == 0) swm[t >> 5] = mymax;
    if (t == 0) s_best = 0ull;
    __syncthreads();

    if (t == 0) {
        uint32_t mmax = swm[0];
#pragma unroll
        for (int w = 1; w < TPB / 32; w++) mmax = max(mmax, swm[w]);
        uint32_t mm9 = mmax >> 9;
        // Candidate window in u-space: u_t = u_max^{exp(W)}, W = range/sigma + slack.
        // MUFU-fast with 64-tick downward slack: threshold is only a pruning
        // bound — pass-2 exact eval decides the argmax.
        float W  = (dec_f(g_mx_u) - dec_f(g_mn_u)) * (1.0f / SIGMA_F) + 2e-3f;
        float um = fmaxf(__uint_as_float(mm9 | 0x3f800000u) - 1.0f, 1e-30f);
        float ut = __expf(__expf(W) * __logf(um));
        long long mt = (long long)floorf(ut * 8388608.0f) - 64;
        if (mt < 0) mt = 0;
        if ((unsigned long long)mt > mm9) mt = mm9;
        s_mt9 = (uint32_t)mt << 9;
    }
    __syncthreads();

    const uint32_t mt9 = s_mt9;
    unsigned long long best = 0ull;
#pragma unroll
    for (int j = 0; j < DPT; j++) {
        if (m[j] >= mt9) {
            uint32_t d = (uint32_t)t * DPT + j;
            float g = gumbel_f32(m[j]);
            // z exactly as XLA: separate f32 mul + add (no FMA contraction)
            float z = __fadd_rn(logits[k * DDIM + (int)d], __fmul_rn(SIGMA_F, g));
            uint32_t oz = __float_as_uint(z);
            oz = (oz & 0x80000000u) ? ~oz : (oz | 0x80000000u);  // order-preserving
            unsigned long long key =
                ((unsigned long long)oz << 32) | (uint32_t)(0xFFFFFFFFu - d);
            best = max(best, key);   // tie -> lowest index wins
        }
    }
    for (int o = 16; o; o >>= 1) best = max(best, __shfl_xor_sync(~0u, best, o));
    if ((t & 31) == 0) atomicMax(&s_best, best);
    __syncthreads();
    if (t == 0) {
        int d = (int)(0xFFFFFFFFu - (uint32_t)(s_best & 0xFFFFFFFFu));
        atomicAdd(&g_counts[(k << 12) + d], 1);
    }
}

// ---------------------------------------------------------------- launch 5
__global__ void build_st_kernel() {
    int i = blockIdx.x * blockDim.x + threadIdx.x;   // i = k*4096 + d
    if (i < KOUT * DDIM) {
        int k = i >> 12, d = i & (DDIM - 1);
        g_St[d * KOUT + k] = (float)g_counts[i] * 0.001f;
    }
}

// ---------------------------------------------------------------- launch 6
// Y[2048,64] = X[2048,4096] @ St[4096,64]. 32x64 CTA tile, 256 threads,
// thread tile 2x4, float4 global loads.
#define TB_M 32
#define DC   64

__global__ __launch_bounds__(256) void gemm_kernel(const float* __restrict__ X,
                                                   float* __restrict__ Y) {
    __shared__ float Xs[TB_M][DC + 4];     // stride 68 floats (16B-aligned rows)
    __shared__ float Ss[DC][KOUT + 4];
    const int t = threadIdx.x;
    const int brow0 = blockIdx.x * TB_M;
    const int tr = t >> 4;          // 0..15 -> rows tr*2, tr*2+1
    const int tk = t & 15;          // 0..15 -> cols tk*4 .. tk*4+3
    float acc[2][4] = {};

    for (int d0 = 0; d0 < DDIM; d0 += DC) {
#pragma unroll
        for (int l = 0; l < 2; l++) {          // 32*64 floats = 512 float4
            int v = t + l * 256;
            int r = v >> 4, c = (v & 15) * 4;
            float4 x = *(const float4*)&X[(brow0 + r) * DDIM + d0 + c];
            *(float4*)&Xs[r][c] = x;
        }
#pragma unroll
        for (int l = 0; l < 4; l++) {          // 64*64 floats = 1024 float4
            int v = t + l * 256;
            int r = v >> 4, c = (v & 15) * 4;
            float4 s = *(const float4*)&g_St[(d0 + r) * KOUT + c];
            *(float4*)&Ss[r][c] = s;
        }
        __syncthreads();
#pragma unroll
        for (int dd = 0; dd < DC; dd++) {
            float x0 = Xs[tr * 2 + 0][dd];
            float x1 = Xs[tr * 2 + 1][dd];
            float4 s = *(const float4*)&Ss[dd][tk * 4];
            acc[0][0] += x0 * s.x; acc[0][1] += x0 * s.y;
            acc[0][2] += x0 * s.z; acc[0][3] += x0 * s.w;
            acc[1][0] += x1 * s.x; acc[1][1] += x1 * s.y;
            acc[1][2] += x1 * s.z; acc[1][3] += x1 * s.w;
        }
        __syncthreads();
    }
#pragma unroll
    for (int r = 0; r < 2; r++)
#pragma unroll
        for (int c = 0; c < 4; c++)
            Y[(brow0 + tr * 2 + r) * KOUT + tk * 4 + c] = acc[r][c];
}

// ---------------------------------------------------------------------------
extern "C" void kernel_launch(void* const* d_in, const int* in_sizes, int n_in,
                              void* d_out, int out_size) {
    const float* X = (const float*)d_in[0];
    const float* logits = (const float*)d_in[1];
    if (n_in >= 2 && in_sizes[0] == KOUT * DDIM) {   // defensive: swapped order
        X = (const float*)d_in[1];
        logits = (const float*)d_in[0];
    }
    float* Y = (float*)d_out;

    range_kernel<<<64, 256>>>(logits);                       // 1
    zero_half_kernel<<<512, 256>>>(0);                       // 2
    zero_half_kernel<<<512, 256>>>(KOUT * DDIM / 2);         // 3
    argmax_kernel<<<NROWS, TPB>>>(logits);                   // 4  <- ncu slot
    build_st_kernel<<<(KOUT * DDIM + 255) / 256, 256>>>();   // 5
    gemm_kernel<<<BATCH / TB_M, 256>>>(X, Y);                // 6
}

// round 9
// speedup vs baseline: 1.0553x; 1.0399x over previous
#include <cuda_runtime.h>
#include <cstdint>
#include <math.h>

// ---------------------------------------------------------------------------
// PerturbedSelect (verified R2-R8, rel_err 5.6e-7):
//   bits[i] = o0^o1 of threefry2x32((0,42),(0,i))   [jax partitionable PRNG]
//   g = -log(-log(u(bits))) ; idx = argmax_d logits[k,d] + sigma*g
//   S[k,d] = count/1000 ; Y = X @ S^T
// R9: integer Bernoulli threshold (no per-row MUFU, one less barrier),
//     thread-level pass-2 guard, split-D GEMM (512 CTAs) + deterministic
//     reduce. argmax kept at launch slot #4 for ncu.
// ---------------------------------------------------------------------------

#define NSAMP 1000
#define KOUT  64
#define DDIM  4096
#define BATCH 2048
#define NROWS (NSAMP * KOUT)          /* 64000 */
#define NSPLIT 4
#define DCHUNK (DDIM / NSPLIT)        /* 1024 */

__device__ int      g_counts[KOUT * DDIM];
__device__ float    g_St[DDIM * KOUT];
__device__ float    g_Ypart[NSPLIT * BATCH * KOUT];
// Range atomics are idempotent across graph replays (same data -> same
// min/max), so static init is sufficient; no per-run reset.
__device__ uint32_t g_mn_u = 0xFFFFFFFFu;
__device__ uint32_t g_mx_u = 0u;
__device__ uint32_t g_E;              // ceil(exp(W) * 2^16) + margin

static __device__ __forceinline__ uint32_t enc_f(float x) {
    uint32_t u = __float_as_uint(x);
    return (u & 0x80000000u) ? ~u : (u | 0x80000000u);
}
static __device__ __forceinline__ float dec_f(uint32_t e) {
    uint32_t u = (e & 0x80000000u) ? (e ^ 0x80000000u) : ~e;
    return __uint_as_float(u);
}

static __device__ __forceinline__ uint32_t rotl32(uint32_t x, int d) {
    return __funnelshift_l(x, x, d);
}

// Threefry-2x32, 20 rounds, key (0, 42) — matches jax threefry2x32 lowering.
// Plain C++: ptxas picks the IMAD/IADD3 mix (proven fastest; forced-IMAD
// regressed in R4).
static __device__ __forceinline__ void threefry(uint32_t x0, uint32_t x1,
                                                uint32_t& o0, uint32_t& o1) {
    const uint32_t k0 = 0u, k1 = 42u, k2 = 0u ^ 42u ^ 0x1BD11BDAu;
    x0 += k0; x1 += k1;
#define RND(r) { x0 += x1; x1 = rotl32(x1, r); x1 ^= x0; }
    RND(13) RND(15) RND(26) RND(6)
    x0 += k1; x1 += k2 + 1u;
    RND(17) RND(29) RND(16) RND(24)
    x0 += k2; x1 += k0 + 2u;
    RND(13) RND(15) RND(26) RND(6)
    x0 += k0; x1 += k1 + 3u;
    RND(17) RND(29) RND(16) RND(24)
    x0 += k1; x1 += k2 + 4u;
    RND(13) RND(15) RND(26) RND(6)
    x0 += k2; x1 += k0 + 5u;
#undef RND
    o0 = x0; o1 = x1;
}

// Exact jax gumbel from raw bits; double logs are correctly rounded and
// immune to --use_fast_math. Used ONLY for the rare candidates (~1-2/row).
static __device__ __forceinline__ float gumbel_f32(uint32_t bits) {
    const float tiny = 1.17549435082228751e-38f;
    float f = __uint_as_float((bits >> 9) | 0x3f800000u) - 1.0f;  // exact
    float u = fmaxf(tiny, __fadd_rn(f, tiny));
    float L1 = (float)log((double)u);
    float L2 = (float)log((double)(-L1));
    return -L2;
}

#define SIGMA_F ((float)(10.0 * 0.99998))

// ---------------------------------------------------------------- launch 1
__global__ void range_kernel(const float* __restrict__ logits) {
    float mn = 3.4e38f, mx = -3.4e38f;
    for (int i = blockIdx.x * blockDim.x + threadIdx.x; i < KOUT * DDIM;
         i += gridDim.x * blockDim.x) {
        float v = logits[i];
        mn = fminf(mn, v); mx = fmaxf(mx, v);
    }
    for (int o = 16; o; o >>= 1) {
        mn = fminf(mn, __shfl_xor_sync(~0u, mn, o));
        mx = fmaxf(mx, __shfl_xor_sync(~0u, mx, o));
    }
    if ((threadIdx.x & 31) == 0) {
        atomicMin(&g_mn_u, enc_f(mn));
        atomicMax(&g_mx_u, enc_f(mx));
    }
}

// ---------------------------------------------------------------- launch 2
// Zero counts; thread 0 finalizes E (range_kernel completed: same stream).
__global__ void zero_kernel() {
    int i = blockIdx.x * blockDim.x + threadIdx.x;
    if (i < KOUT * DDIM) g_counts[i] = 0;
    if (i == 0) {
        float W = (dec_f(g_mx_u) - dec_f(g_mn_u)) * (1.0f / SIGMA_F) + 2e-3f;
        g_E = (uint32_t)(__expf(W) * 65536.0f) + 16u;   // >= exp(W)*2^16
    }
}

// ---------------------------------------------------------------- launch 3
__global__ void pad_kernel() {}   // slot padding so argmax is launch #4

// ---------------------------------------------------------------- launch 4
// One CTA per (sample,k) row. Pass 1: threefry all 4096 bits into registers,
// integer max over raw bits. Integer Bernoulli threshold (u^a >= 1-a(1-u),
// a = e^W >= 1, conservative) selects ~1-2 candidates/row for exact eval.
#define TPB 256
#define DPT (DDIM / TPB)   /* 16 */

__global__ __launch_bounds__(TPB) void argmax_kernel(const float* __restrict__ logits) {
    const int row = blockIdx.x;
    const int k = row & (KOUT - 1);
    const uint32_t base = (uint32_t)row * (uint32_t)DDIM;   // < 2^32
    const int t = threadIdx.x;

    uint32_t m[DPT];
#pragma unroll
    for (int j = 0; j < DPT; j++) {
        uint32_t i = base + (uint32_t)t * DPT + j;
        uint32_t o0, o1;
        threefry(0u, i, o0, o1);
        m[j] = o0 ^ o1;                 // raw 32-bit; order == (m>>9) order
    }

    // per-thread tree max (kept for the pass-2 guard)
    uint32_t r8[8];
#pragma unroll
    for (int j = 0; j < 8; j++) r8[j] = max(m[j], m[j + 8]);
#pragma unroll
    for (int j = 0; j < 4; j++) r8[j] = max(r8[j], r8[j + 4]);
    const uint32_t tmax = max(max(r8[0], r8[1]), max(r8[2], r8[3]));

    uint32_t wmax = tmax;
    for (int o = 16; o; o >>= 1) wmax = max(wmax, __shfl_xor_sync(~0u, wmax, o));

    __shared__ uint32_t swm[TPB / 32];
    __shared__ unsigned long long s_best;
    if ((t & 31) == 0) swm[t >> 5] = wmax;
    if (t == 0) s_best = 0ull;
    __syncthreads();

    // CTA max + integer threshold, computed redundantly by every thread
    // (no serial section, no second broadcast barrier).
    uint32_t mmax = swm[0];
#pragma unroll
    for (int w = 1; w < TPB / 32; w++) mmax = max(mmax, swm[w]);
    const uint32_t mm9 = mmax >> 9;
    // u^a >= 1 - a(1-u) for a>=1: threshold sits BELOW the true window edge.
    uint32_t red = (uint32_t)(((unsigned long long)g_E *
                               (unsigned long long)(0x800000u - mm9)) >> 16);
    int mt = 0x800000 - (int)red - 256;     // 256-tick extra slack
    if (mt < 0) mt = 0;
    const uint32_t mt9 = (uint32_t)mt << 9; // <= mmax: >=1 candidate per row

    unsigned long long best = 0ull;
    if (tmax >= mt9) {                      // rare: ~1-2 threads per row
#pragma unroll
        for (int j = 0; j < DPT; j++) {
            if (m[j] >= mt9) {
                uint32_t d = (uint32_t)t * DPT + j;
                float g = gumbel_f32(m[j]);
                // z exactly as XLA: separate f32 mul + add (no FMA contraction)
                float z = __fadd_rn(logits[k * DDIM + (int)d], __fmul_rn(SIGMA_F, g));
                uint32_t oz = __float_as_uint(z);
                oz = (oz & 0x80000000u) ? ~oz : (oz | 0x80000000u);
                unsigned long long key =
                    ((unsigned long long)oz << 32) | (uint32_t)(0xFFFFFFFFu - d);
                best = max(best, key);      // tie -> lowest index wins
            }
        }
    }
    for (int o = 16; o; o >>= 1) best = max(best, __shfl_xor_sync(~0u, best, o));
    if ((t & 31) == 0 && best) atomicMax(&s_best, best);
    __syncthreads();
    if (t == 0) {
        int d = (int)(0xFFFFFFFFu - (uint32_t)(s_best & 0xFFFFFFFFu));
        atomicAdd(&g_counts[(k << 12) + d], 1);
    }
}

// ---------------------------------------------------------------- launch 5
__global__ void build_st_kernel() {
    int i = blockIdx.x * blockDim.x + threadIdx.x;   // i = k*4096 + d
    if (i < KOUT * DDIM) {
        int k = i >> 12, d = i & (DDIM - 1);
        g_St[d * KOUT + k] = (float)g_counts[i] * 0.001f;
    }
}

// ---------------------------------------------------------------- launch 6
// Partial GEMM: Ypart[s] = X[:, s*1024:(s+1)*1024] @ St[s-chunk].
// grid (BATCH/TB_M, NSPLIT) = (128, 4) = 512 CTAs, 256 threads each.
#define TB_M 16
#define DC   64

__global__ __launch_bounds__(256) void gemm_partial_kernel(const float* __restrict__ X) {
    __shared__ float Xs[TB_M][DC + 4];
    __shared__ float Ss[DC][KOUT + 4];
    const int t = threadIdx.x;
    const int brow0 = blockIdx.x * TB_M;
    const int s = blockIdx.y;
    const int tr = t >> 4;          // 0..15 -> row tr
    const int tk = t & 15;          // 0..15 -> cols tk*4 .. tk*4+3
    float acc[4] = {};

    for (int d0 = s * DCHUNK; d0 < (s + 1) * DCHUNK; d0 += DC) {
        {                                   // 16*64 floats = 256 float4
            int v = t;                      // v in [0,256): r=v>>4, c=(v&15)*4
            float4 x = *(const float4*)&X[(brow0 + (v >> 4)) * DDIM + d0 + (v & 15) * 4];
            *(float4*)&Xs[v >> 4][(v & 15) * 4] = x;
        }
#pragma unroll
        for (int l = 0; l < 4; l++) {       // 64*64 floats = 1024 float4
            int v = t + l * 256;
            float4 w = *(const float4*)&g_St[(d0 + (v >> 4)) * KOUT + (v & 15) * 4];
            *(float4*)&Ss[v >> 4][(v & 15) * 4] = w;
        }
        __syncthreads();
#pragma unroll
        for (int dd = 0; dd < DC; dd++) {
            float x0 = Xs[tr][dd];
            float4 w = *(const float4*)&Ss[dd][tk * 4];
            acc[0] += x0 * w.x; acc[1] += x0 * w.y;
            acc[2] += x0 * w.z; acc[3] += x0 * w.w;
        }
        __syncthreads();
    }
#pragma unroll
    for (int c = 0; c < 4; c++)
        g_Ypart[(s * BATCH + brow0 + tr) * KOUT + tk * 4 + c] = acc[c];
}

// ---------------------------------------------------------------- launch 7
// Deterministic fixed-order reduction of the 4 partials.
__global__ void reduce_y_kernel(float* __restrict__ Y) {
    int i = blockIdx.x * blockDim.x + threadIdx.x;
    if (i < BATCH * KOUT) {
        const int N = BATCH * KOUT;
        float v = ((g_Ypart[i] + g_Ypart[N + i]) + g_Ypart[2 * N + i])
                  + g_Ypart[3 * N + i];
        Y[i] = v;
    }
}

// ---------------------------------------------------------------------------
extern "C" void kernel_launch(void* const* d_in, const int* in_sizes, int n_in,
                              void* d_out, int out_size) {
    const float* X = (const float*)d_in[0];
    const float* logits = (const float*)d_in[1];
    if (n_in >= 2 && in_sizes[0] == KOUT * DDIM) {   // defensive: swapped order
        X = (const float*)d_in[1];
        logits = (const float*)d_in[0];
    }
    float* Y = (float*)d_out;

    range_kernel<<<64, 256>>>(logits);                       // 1
    zero_kernel<<<1024, 256>>>();                            // 2
    pad_kernel<<<1, 32>>>();                                 // 3
    argmax_kernel<<<NROWS, TPB>>>(logits);                   // 4  <- ncu slot
    build_st_kernel<<<1024, 256>>>();                        // 5
    {
        dim3 grid(BATCH / TB_M, NSPLIT);
        gemm_partial_kernel<<<grid, 256>>>(X);               // 6
    }
    reduce_y_kernel<<<(BATCH * KOUT + 255) / 256, 256>>>(Y); // 7
}